// round 5
// baseline (speedup 1.0000x reference)
#include <cuda_runtime.h>

// Problem constants
#define DIM   (1 << 22)        // 2^22 = 4194304
#define BATCH 16
#define HALF4 ((DIM / 2) * BATCH / 4)   // 8388608 float4s per half-state
#define TPB   256
#define QUARTER4 (HALF4 / 2)            // second chunk offset for 2x work/thread

// Fused streaming rotation, 2 row-pairs per thread (MLP=8 front-batched
// 128-bit loads). Thread t handles float4 indices u=t and v=t+QUARTER4 in the
// lower half, each paired with +HALF4 in the upper half. All accesses fully
// coalesced. Trig (16 cos/sin) broadcast via smem, loads issued before the
// barrier so memory latency overlaps it.
//
// Memory layout (float4 index space, H = HALF4):
//   inputs : re[x], re[x+H], im[x], im[x+H]        for x in {u, v}
//   outputs: out_re lower = out[x], out_re upper = out[x+H]
//            out_im lower = out[2H+x], out_im upper = out[3H+x]
__global__ __launch_bounds__(TPB) void rot_kernel(
    const float* __restrict__ theta,
    const float4* __restrict__ re,
    const float4* __restrict__ im,
    float4* __restrict__ out)
{
    __shared__ float sc[BATCH];
    __shared__ float ss[BATCH];

    int t = blockIdx.x * TPB + threadIdx.x;
    int u = t;
    int v = t + QUARTER4;

    // 8 independent 128-bit loads issued first (latency overlapped with trig)
    float4 a_re0 = re[u];
    float4 a_re1 = re[u + HALF4];
    float4 a_im0 = im[u];
    float4 a_im1 = im[u + HALF4];
    float4 b_re0 = re[v];
    float4 b_re1 = re[v + HALF4];
    float4 b_im0 = im[v];
    float4 b_im1 = im[v + HALF4];

    if (threadIdx.x < BATCH) {
        float th = theta[threadIdx.x] * 0.5f;  // L2-resident after first wave
        sc[threadIdx.x] = cosf(th);
        ss[threadIdx.x] = sinf(th);
    }
    __syncthreads();

    int b4 = t & 3;  // which float4 within the 16-wide batch row (same for u,v)
    float4 c = reinterpret_cast<const float4*>(sc)[b4];
    float4 s = reinterpret_cast<const float4*>(ss)[b4];

    float4 a_or0, a_or1, a_oi0, a_oi1;
    float4 b_or0, b_or1, b_oi0, b_oi1;
#define ROT_COMP(p, f)                                          \
    p##_or0.f = fmaf(c.f, p##_re0.f,  s.f * p##_im1.f);         \
    p##_oi0.f = fmaf(c.f, p##_im0.f, -s.f * p##_re1.f);         \
    p##_or1.f = fmaf(c.f, p##_re1.f,  s.f * p##_im0.f);         \
    p##_oi1.f = fmaf(c.f, p##_im1.f, -s.f * p##_re0.f);
    ROT_COMP(a, x) ROT_COMP(a, y) ROT_COMP(a, z) ROT_COMP(a, w)
    ROT_COMP(b, x) ROT_COMP(b, y) ROT_COMP(b, z) ROT_COMP(b, w)
#undef ROT_COMP

    out[u]             = a_or0;
    out[u + HALF4]     = a_or1;
    out[2 * HALF4 + u] = a_oi0;
    out[3 * HALF4 + u] = a_oi1;
    out[v]             = b_or0;
    out[v + HALF4]     = b_or1;
    out[2 * HALF4 + v] = b_oi0;
    out[3 * HALF4 + v] = b_oi1;
}

extern "C" void kernel_launch(void* const* d_in, const int* in_sizes, int n_in,
                              void* d_out, int out_size) {
    const float* theta = (const float*)d_in[0];
    const float4* re   = (const float4*)d_in[1];
    const float4* im   = (const float4*)d_in[2];
    float4* out        = (float4*)d_out;

    rot_kernel<<<QUARTER4 / TPB, TPB>>>(theta, re, im, out);
}

// round 6
// speedup vs baseline: 1.0033x; 1.0033x over previous
#include <cuda_runtime.h>

// Problem constants
#define DIM   (1 << 22)        // 2^22 = 4194304
#define BATCH 16
#define H8    ((DIM / 2) * BATCH / 8)   // 4194304 float8s per half-state
#define TPB   256

// 256-bit global load/store (sm_100+/sm_103a: LDG.E.256 / STG.E.256).
__device__ __forceinline__ void ldg256(const float* __restrict__ p, float v[8]) {
    asm("ld.global.v8.f32 {%0,%1,%2,%3,%4,%5,%6,%7}, [%8];"
        : "=f"(v[0]), "=f"(v[1]), "=f"(v[2]), "=f"(v[3]),
          "=f"(v[4]), "=f"(v[5]), "=f"(v[6]), "=f"(v[7])
        : "l"(p));
}
__device__ __forceinline__ void stg256(float* p, const float v[8]) {
    asm volatile("st.global.v8.f32 [%0], {%1,%2,%3,%4,%5,%6,%7,%8};"
        :: "l"(p),
           "f"(v[0]), "f"(v[1]), "f"(v[2]), "f"(v[3]),
           "f"(v[4]), "f"(v[5]), "f"(v[6]), "f"(v[7])
        : "memory");
}

// Fused streaming rotation with 256-bit accesses. Thread t owns one float8
// (8 of the 16 batch entries) of row j in the lower half, paired with row
// j + DIM/2. 4x LDG.256 front-batched, latency overlapped with the trig
// broadcast, then 4x STG.256.
//
// Memory layout (float8 index space, H = H8):
//   inputs : re[t], re[t+H], im[t], im[t+H]
//   outputs: out_re lower = out[t], out_re upper = out[t+H]
//            out_im lower = out[2H+t], out_im upper = out[3H+t]
__global__ __launch_bounds__(TPB) void rot_kernel(
    const float* __restrict__ theta,
    const float* __restrict__ re,
    const float* __restrict__ im,
    float* __restrict__ out)
{
    __shared__ float sc[BATCH];
    __shared__ float ss[BATCH];

    long long t = (long long)blockIdx.x * TPB + threadIdx.x;

    // 4 independent 256-bit loads issued first (overlap with trig + barrier)
    float re0[8], re1[8], im0[8], im1[8];
    ldg256(re + t * 8,              re0);
    ldg256(re + (t + H8) * 8,       re1);
    ldg256(im + t * 8,              im0);
    ldg256(im + (t + H8) * 8,       im1);

    if (threadIdx.x < BATCH) {
        float th = theta[threadIdx.x] * 0.5f;  // L2-resident after first wave
        sc[threadIdx.x] = cosf(th);
        ss[threadIdx.x] = sinf(th);
    }
    __syncthreads();

    int b8 = (int)(t & 1) * 8;  // which float8 within the 16-wide batch row

    float or0[8], or1[8], oi0[8], oi1[8];
#pragma unroll
    for (int i = 0; i < 8; i++) {
        float c = sc[b8 + i];
        float s = ss[b8 + i];
        or0[i] = fmaf(c, re0[i],  s * im1[i]);
        oi0[i] = fmaf(c, im0[i], -s * re1[i]);
        or1[i] = fmaf(c, re1[i],  s * im0[i]);
        oi1[i] = fmaf(c, im1[i], -s * re0[i]);
    }

    stg256(out + t * 8,                  or0);
    stg256(out + (t + H8) * 8,           or1);
    stg256(out + (2LL * H8 + t) * 8,     oi0);
    stg256(out + (3LL * H8 + t) * 8,     oi1);
}

extern "C" void kernel_launch(void* const* d_in, const int* in_sizes, int n_in,
                              void* d_out, int out_size) {
    const float* theta = (const float*)d_in[0];
    const float* re    = (const float*)d_in[1];
    const float* im    = (const float*)d_in[2];
    float* out         = (float*)d_out;

    rot_kernel<<<H8 / TPB, TPB>>>(theta, re, im, out);
}